// round 8
// baseline (speedup 1.0000x reference)
#include <cuda_runtime.h>
#include <cstdint>

#define BB 256
#define TT 512
#define IND 64
#define HH 512
#define GG 2048   // 4*H
#define NCTA 128

// ---------------- device scratch ----------------
__device__ float g_xproj[(size_t)TT * BB * GG];   // layer-0 x-projection (+bias0)
__device__ float g_hseq [(size_t)TT * BB * HH];   // h0 history (recurrent src + layer-1 input)
__device__ float g_hbuf [2][BB * HH];             // h1 double buffer
__device__ float g_zero [BB * HH];                // h0[-1] = 0
__device__ float g_W0   [GG * HH];                // Whh0, gate-interleaved rows, tf32
__device__ float g_W1cat[(size_t)GG * 1024];      // [Wih1 | Whh1], gate-interleaved, tf32
__device__ float g_Wih0 [GG * IND];
__device__ float g_bias [2][GG];
__device__ unsigned g_cnt[2][4][4];               // [layer][batch-tile][k-group]

// ---------------- helpers ----------------
__device__ __forceinline__ float tf32f(float x) {
    uint32_t u;
    asm("cvt.rna.tf32.f32 %0, %1;" : "=r"(u) : "f"(x));
    return __uint_as_float(u);
}

// pair-fragment mma: thread q supplies k-lanes (q, q+4); adjacent k-pair from
// BOTH operands -> dot product unchanged.
__device__ __forceinline__ void mma_tf32(float* c,
                                         float a0, float a1, float a2, float a3,
                                         float b0, float b1) {
    asm volatile(
        "mma.sync.aligned.m16n8k8.row.col.f32.tf32.tf32.f32 "
        "{%0,%1,%2,%3}, {%4,%5,%6,%7}, {%8,%9}, {%0,%1,%2,%3};\n"
        : "+f"(c[0]), "+f"(c[1]), "+f"(c[2]), "+f"(c[3])
        : "r"(__float_as_uint(a0)), "r"(__float_as_uint(a1)),
          "r"(__float_as_uint(a2)), "r"(__float_as_uint(a3)),
          "r"(__float_as_uint(b0)), "r"(__float_as_uint(b1)));
}

__device__ __forceinline__ float fsigm(float x) {
    return __fdividef(1.0f, 1.0f + __expf(-x));
}
__device__ __forceinline__ float ftanh(float x) {
    return 2.0f * __fdividef(1.0f, 1.0f + __expf(-2.0f * x)) - 1.0f;
}

__device__ __forceinline__ void cpasync16(uint32_t saddr, const void* g) {
    asm volatile("cp.async.cg.shared.global [%0], [%1], 16;\n" :: "r"(saddr), "l"(g));
}
__device__ __forceinline__ void cpasync_commit() {
    asm volatile("cp.async.commit_group;\n");
}
template <int N> __device__ __forceinline__ void cpasync_wait() {
    asm volatile("cp.async.wait_group %0;\n" :: "n"(N) : "memory");
}

__device__ __forceinline__ unsigned ld_acq(const unsigned* p) {
    unsigned v;
    asm volatile("ld.acquire.gpu.global.u32 %0, [%1];" : "=r"(v) : "l"(p) : "memory");
    return v;
}
__device__ __forceinline__ void wait_cnt(const unsigned* p, unsigned thr) {
    if (ld_acq(p) >= thr) return;
    while (ld_acq(p) < thr) __nanosleep(32);
}

// ---------------- weight permute + tf32 pre-round ----------------
__global__ void prep_kernel(const float* __restrict__ Wih0, const float* __restrict__ Whh0,
                            const float* __restrict__ bih0, const float* __restrict__ bhh0,
                            const float* __restrict__ Wih1, const float* __restrict__ Whh1,
                            const float* __restrict__ bih1, const float* __restrict__ bhh1) {
    int stride = gridDim.x * blockDim.x;
    int tid = blockIdx.x * blockDim.x + threadIdx.x;
    if (blockIdx.x == 0 && threadIdx.x < 32) {
        ((unsigned*)g_cnt)[threadIdx.x] = 0u;
    }
    for (int i = tid; i < GG * HH; i += stride) {
        int orow = i / HH, k = i - orow * HH;
        int j = orow >> 2, gate = orow & 3;
        int src = (gate * HH + j) * HH + k;
        int prow = j * 4 + gate;
        g_W0[i] = tf32f(Whh0[src]);
        g_W1cat[(size_t)prow * 1024 + k]       = tf32f(Wih1[src]);
        g_W1cat[(size_t)prow * 1024 + 512 + k] = tf32f(Whh1[src]);
    }
    for (int i = tid; i < GG * IND; i += stride) {
        int orow = i / IND, k = i - orow * IND;
        int j = orow >> 2, gate = orow & 3;
        g_Wih0[i] = tf32f(Wih0[(gate * HH + j) * IND + k]);
    }
    for (int i = tid; i < GG; i += stride) {
        int j = i >> 2, gate = i & 3;
        int src = gate * HH + j;
        g_bias[0][i] = bih0[src] + bhh0[src];
        g_bias[1][i] = bih1[src] + bhh1[src];
    }
    for (int i = tid; i < BB * HH; i += stride) g_zero[i] = 0.0f;
}

// ---------------- layer-0 input projection (K=64) ----------------
#define KC 64
__global__ void __launch_bounds__(256)
inproj0_kernel(const float* __restrict__ x) {
    __shared__ float sA[64][KC + 4];
    __shared__ float sB[64][KC + 4];

    const float* __restrict__ W    = g_Wih0;
    const float* __restrict__ bias = g_bias[0];

    int tid = threadIdx.x;
    int m0 = blockIdx.x * 64;
    int n0 = blockIdx.y * 64;
    int t  = m0 >> 8;
    int b0 = m0 & 255;
    const float* Abase = x + (size_t)b0 * TT * IND + (size_t)t * IND;

    int w = tid >> 5, lane = tid & 31, q = lane & 3, gq = lane >> 2;
    int wm = w & 3, wn = w >> 2;

    float acc[4][4] = {};

#pragma unroll
    for (int r = 0; r < 4; r++) {
        int idx = tid + r * 256;
        int row = idx >> 4;
        int c4  = idx & 15;
        float4 v = *reinterpret_cast<const float4*>(Abase + (size_t)row * TT * IND + c4 * 4);
        v.x = tf32f(v.x); v.y = tf32f(v.y); v.z = tf32f(v.z); v.w = tf32f(v.w);
        *reinterpret_cast<float4*>(&sA[row][c4 * 4]) = v;
        float4 wv = *reinterpret_cast<const float4*>(W + (long)(n0 + row) * IND + c4 * 4);
        *reinterpret_cast<float4*>(&sB[row][c4 * 4]) = wv;
    }
    __syncthreads();
#pragma unroll
    for (int ks = 0; ks < KC / 8; ks++) {
        int k0 = ks * 8;
        float a0 = sA[wm * 16 + gq    ][k0 + q];
        float a1 = sA[wm * 16 + gq + 8][k0 + q];
        float a2 = sA[wm * 16 + gq    ][k0 + q + 4];
        float a3 = sA[wm * 16 + gq + 8][k0 + q + 4];
#pragma unroll
        for (int nt = 0; nt < 4; nt++) {
            int n = wn * 32 + nt * 8 + gq;
            mma_tf32(acc[nt], a0, a1, a2, a3, sB[n][k0 + q], sB[n][k0 + q + 4]);
        }
    }

#pragma unroll
    for (int nt = 0; nt < 4; nt++) {
        int col = n0 + wn * 32 + nt * 8 + q * 2;
        float bv0 = bias[col], bv1 = bias[col + 1];
        int row = m0 + wm * 16 + gq;
        *reinterpret_cast<float2*>(g_xproj + (size_t)row * GG + col) =
            make_float2(acc[nt][0] + bv0, acc[nt][1] + bv1);
        *reinterpret_cast<float2*>(g_xproj + (size_t)(row + 8) * GG + col) =
            make_float2(acc[nt][2] + bv0, acc[nt][3] + bv1);
    }
}

// ---------------- fused 2-layer pipelined persistent scan ----------------
// CTA (bi, ni): batch tile 64 x gate tile 64 for BOTH layers.
// Iteration it: layer-0 step it (if it<TT), layer-1 step it-1 (if it>=1).
// 8 k-passes of 128: passes 0-3 stream h0[it-1] -> acc0 (Whh0) AND acc1 (Wih1);
// passes 4-7 stream h1[it-2] -> acc1 (Whh1). W1cat rows = [Wih1 | Whh1].
#define APAD 136
#define XPAD 68
#define GPAD 72
#define BUF_F (64 * APAD)       // 8704 floats per buffer
#define SMEM_SCAN ((6 * BUF_F + 64 * XPAD) * 4)   // 226304 B

__global__ void __launch_bounds__(256, 1)
fused_scan_kernel() {
    extern __shared__ float sm[];
    float* W0b[2] = { sm,             sm + BUF_F };
    float* W1b[2] = { sm + 2 * BUF_F, sm + 3 * BUF_F };
    float* Ab [2] = { sm + 4 * BUF_F, sm + 5 * BUF_F };
    float* sXP    = sm + 6 * BUF_F;
    uint32_t W0u[2], W1u[2], Au[2], XPu;
#pragma unroll
    for (int i = 0; i < 2; i++) {
        W0u[i] = (uint32_t)__cvta_generic_to_shared(W0b[i]);
        W1u[i] = (uint32_t)__cvta_generic_to_shared(W1b[i]);
        Au[i]  = (uint32_t)__cvta_generic_to_shared(Ab[i]);
    }
    XPu = (uint32_t)__cvta_generic_to_shared(sXP);

    int tid = threadIdx.x, w = tid >> 5, lane = tid & 31, q = lane & 3, gq = lane >> 2;
    int wm = w & 1, wn = w >> 1;             // 8 warps: 32-row x 16-col tiles
    int bi = blockIdx.x & 3, ni = blockIdx.x >> 2;
    int b0 = bi * 64, n0 = ni * 64, j0 = ni * 16;

    unsigned* mc0 = &g_cnt[0][bi][ni >> 3];
    unsigned* mc1 = &g_cnt[1][bi][ni >> 3];
    const unsigned* cb0 = g_cnt[0][bi];
    const unsigned* cb1 = g_cnt[1][bi];

    const float* W0src = g_W0 + (size_t)n0 * HH;
    const float* W1src = g_W1cat + (size_t)n0 * 1024;

    // per-thread epilogue slot: b = (tid>>4) + s*16, j = tid&15 (const over s)
    const float4 bias4 = *reinterpret_cast<const float4*>(g_bias[1] + (j0 + (tid & 15)) * 4);

    // init: zero h1[-1] slice (hbuf[1]); c-states
    float c0r[4], c1r[4];
#pragma unroll
    for (int s = 0; s < 4; s++) {
        c0r[s] = 0.0f; c1r[s] = 0.0f;
        int idx = tid + s * 256;
        g_hbuf[1][(b0 + (idx >> 4)) * HH + j0 + (idx & 15)] = 0.0f;
    }
    __threadfence();
    __syncthreads();
    if (tid == 0) { atomicAdd(mc0, 1u); atomicAdd(mc1, 1u); }

    // 64x128 tile loader (rows x 128 floats), dst stride APAD
    auto load_tile = [&](uint32_t dstu, const float* src, long rstride) {
#pragma unroll
        for (int r = 0; r < 8; r++) {
            int idx = tid + r * 256;
            int row = idx >> 5, c4 = idx & 31;
            cpasync16(dstu + (row * APAD + c4 * 4) * 4, src + (long)row * rstride + c4 * 4);
        }
    };

    for (int it = 0; it <= TT; ++it) {
        const bool l0 = (it < TT), l1 = (it >= 1);
        const unsigned thr0 = 8u * (unsigned)(it + 1);
        const unsigned thr1 = 8u * (unsigned)it;
        const float* src0 = (it == 0) ? (g_zero + b0 * HH)
                                      : (g_hseq + (size_t)(it - 1) * BB * HH + b0 * HH);
        const float* src1 = g_hbuf[(it - 2) & 1] + b0 * HH;
        const float* xp_t = g_xproj + (size_t)(l0 ? it : 0) * BB * GG;
        float* hseq_it = g_hseq + (size_t)it * BB * HH;
        float* h1out   = g_hbuf[(it - 1) & 1];

        float acc0[2][2][4] = {};
        float acc1[2][2][4] = {};

        // prologue: xp + chunk 0 (A gated; W0/W1 chunk0 were prefetched at prev pass 7)
        wait_cnt(&cb0[0], thr0);
#pragma unroll
        for (int r = 0; r < 4; r++) {
            int idx = tid + r * 256;
            int row = idx >> 4, c4 = idx & 15;
            cpasync16(XPu + (row * XPAD + c4 * 4) * 4,
                      xp_t + (size_t)(b0 + row) * GG + n0 + c4 * 4);
        }
        load_tile(Au[0], src0, HH);
        if (it == 0) { load_tile(W0u[0], W0src, HH); load_tile(W1u[0], W1src, 1024); }
        cpasync_commit();

#pragma unroll
        for (int p = 0; p < 8; ++p) {
            // hoist gate for pass p+1
            if (p < 3)            wait_cnt(&cb0[p + 1], thr0);
            else if (p < 7)       wait_cnt(&cb1[p - 3], thr1);
            cpasync_wait<0>();
            __syncthreads();
            if (p < 7) {
                const float* asrc = (p + 1 < 4) ? src0 + (p + 1) * 128
                                                : src1 + (p - 3) * 128;
                load_tile(Au[(p + 1) & 1], asrc, HH);
                if (p < 3) load_tile(W0u[(p + 1) & 1], W0src + (p + 1) * 128, HH);
                load_tile(W1u[(p + 1) & 1], W1src + (p + 1) * 128, 1024);
                cpasync_commit();
            } else {
                // cross-iteration W prefetch (chunk 0), targets buffers [0]
                load_tile(W0u[0], W0src, HH);
                load_tile(W1u[0], W1src, 1024);
                cpasync_commit();
            }

            const float* cA  = Ab[p & 1]  + (wm * 32) * APAD;
            const float* cW1 = W1b[p & 1] + (wn * 16) * APAD;
            const float* cW0 = W0b[p & 1] + (wn * 16) * APAD;
#pragma unroll 4
            for (int ks = 0; ks < 16; ks++) {
                int k2 = ks * 8 + 2 * q;
                float2 aL0 = *reinterpret_cast<const float2*>(cA + gq * APAD + k2);
                float2 aH0 = *reinterpret_cast<const float2*>(cA + (gq + 8) * APAD + k2);
                float2 aL1 = *reinterpret_cast<const float2*>(cA + (16 + gq) * APAD + k2);
                float2 aH1 = *reinterpret_cast<const float2*>(cA + (24 + gq) * APAD + k2);
#pragma unroll
                for (int nt = 0; nt < 2; nt++) {
                    float2 b1f = *reinterpret_cast<const float2*>(cW1 + (nt * 8 + gq) * APAD + k2);
                    mma_tf32(acc1[0][nt], aL0.x, aH0.x, aL0.y, aH0.y, b1f.x, b1f.y);
                    mma_tf32(acc1[1][nt], aL1.x, aH1.x, aL1.y, aH1.y, b1f.x, b1f.y);
                    if (p < 4 && l0) {
                        float2 b0f = *reinterpret_cast<const float2*>(cW0 + (nt * 8 + gq) * APAD + k2);
                        mma_tf32(acc0[0][nt], aL0.x, aH0.x, aL0.y, aH0.y, b0f.x, b0f.y);
                        mma_tf32(acc0[1][nt], aL1.x, aH1.x, aL1.y, aH1.y, b0f.x, b0f.y);
                    }
                }
            }

            if (p == 3 && l0) {
                // ---- layer-0 epilogue: h0[it] -> hseq[it], signal cnt0 ----
                __syncthreads();                 // all warps done with Ab[1] (pass-3 A)
                float* Gm = Ab[1];
#pragma unroll
                for (int mt = 0; mt < 2; mt++)
#pragma unroll
                    for (int nt = 0; nt < 2; nt++) {
                        int row = wm * 32 + mt * 16 + gq;
                        int col = wn * 16 + nt * 8 + q * 2;
                        *reinterpret_cast<float2*>(&Gm[row * GPAD + col]) =
                            make_float2(acc0[mt][nt][0], acc0[mt][nt][1]);
                        *reinterpret_cast<float2*>(&Gm[(row + 8) * GPAD + col]) =
                            make_float2(acc0[mt][nt][2], acc0[mt][nt][3]);
                    }
                __syncthreads();
#pragma unroll
                for (int s = 0; s < 4; s++) {
                    int idx = tid + s * 256;
                    int b = idx >> 4, j = idx & 15;
                    float4 gm = *reinterpret_cast<float4*>(&Gm[b * GPAD + j * 4]);
                    float4 xp = *reinterpret_cast<float4*>(&sXP[b * XPAD + j * 4]);
                    float I = fsigm(gm.x + xp.x);
                    float F = fsigm(gm.y + xp.y);
                    float G = ftanh(gm.z + xp.z);
                    float O = fsigm(gm.w + xp.w);
                    float cv = F * c0r[s] + I * G;
                    c0r[s] = cv;
                    hseq_it[(b0 + b) * HH + j0 + j] = tf32f(O * ftanh(cv));
                }
                __threadfence();
                __syncthreads();
                if (tid == 0) atomicAdd(mc0, 1u);
            }
        }

        if (l1) {
            // ---- layer-1 epilogue: h1[it-1] -> hbuf[(it-1)&1], signal cnt1 ----
            __syncthreads();                     // all warps done with Ab[1] (pass-7 A)
            float* Gm = Ab[1];
#pragma unroll
            for (int mt = 0; mt < 2; mt++)
#pragma unroll
                for (int nt = 0; nt < 2; nt++) {
                    int row = wm * 32 + mt * 16 + gq;
                    int col = wn * 16 + nt * 8 + q * 2;
                    *reinterpret_cast<float2*>(&Gm[row * GPAD + col]) =
                        make_float2(acc1[mt][nt][0], acc1[mt][nt][1]);
                    *reinterpret_cast<float2*>(&Gm[(row + 8) * GPAD + col]) =
                        make_float2(acc1[mt][nt][2], acc1[mt][nt][3]);
                }
            __syncthreads();
#pragma unroll
            for (int s = 0; s < 4; s++) {
                int idx = tid + s * 256;
                int b = idx >> 4, j = idx & 15;
                float4 gm = *reinterpret_cast<float4*>(&Gm[b * GPAD + j * 4]);
                float I = fsigm(gm.x + bias4.x);
                float F = fsigm(gm.y + bias4.y);
                float G = ftanh(gm.z + bias4.z);
                float O = fsigm(gm.w + bias4.w);
                float cv = F * c1r[s] + I * G;
                c1r[s] = cv;
                h1out[(b0 + b) * HH + j0 + j] = tf32f(O * ftanh(cv));
            }
            __threadfence();
            __syncthreads();
            if (tid == 0) atomicAdd(mc1, 1u);
        }
    }
}

// ---------------- output head ----------------
__global__ void final_kernel(const float* __restrict__ Wout, const float* __restrict__ bout,
                             float* __restrict__ out) {
    __shared__ float sw[HH];
    int tid = threadIdx.x;
    for (int i = tid; i < HH; i += 256) sw[i] = Wout[i];
    __syncthreads();
    const float* h = g_hbuf[1];   // h1[TT-1], (TT-1)&1 = 1
    float s = bout[0];
#pragma unroll 4
    for (int j = 0; j < HH; j++) {
        float v = h[tid * HH + j];
        v = v > 0.0f ? v : 0.0f;
        s += v * sw[j];
    }
    out[tid] = s;
}

// ---------------- launch ----------------
extern "C" void kernel_launch(void* const* d_in, const int* in_sizes, int n_in,
                              void* d_out, int out_size) {
    (void)in_sizes; (void)n_in; (void)out_size;
    const float* x    = (const float*)d_in[0];
    const float* Wih0 = (const float*)d_in[1];
    const float* Whh0 = (const float*)d_in[2];
    const float* bih0 = (const float*)d_in[3];
    const float* bhh0 = (const float*)d_in[4];
    const float* Wih1 = (const float*)d_in[5];
    const float* Whh1 = (const float*)d_in[6];
    const float* bih1 = (const float*)d_in[7];
    const float* bhh1 = (const float*)d_in[8];
    const float* Wout = (const float*)d_in[9];
    const float* bout = (const float*)d_in[10];
    float* out = (float*)d_out;

    cudaFuncSetAttribute(fused_scan_kernel, cudaFuncAttributeMaxDynamicSharedMemorySize, SMEM_SCAN);

    prep_kernel<<<1024, 256>>>(Wih0, Whh0, bih0, bhh0, Wih1, Whh1, bih1, bhh1);
    inproj0_kernel<<<dim3(2048, 32), 256>>>(x);
    fused_scan_kernel<<<NCTA, 256, SMEM_SCAN>>>();
    final_kernel<<<1, 256>>>(Wout, bout, out);
}

// round 9
// speedup vs baseline: 1.0554x; 1.0554x over previous
#include <cuda_runtime.h>
#include <cstdint>

#define BB 256
#define TT 512
#define IND 64
#define HH 512
#define GG 2048   // 4*H
#define NCTA 128

// ---------------- device scratch ----------------
__device__ float g_xproj[(size_t)TT * BB * GG];
__device__ float g_hseq [(size_t)TT * BB * HH];
__device__ float g_hbuf [2][BB * HH];
__device__ float g_Whh  [2][GG * HH];     // gate-interleaved rows, tf32-rounded
__device__ float g_Wih0 [GG * IND];
__device__ float g_Wih1 [GG * HH];
__device__ float g_bias [2][GG];
__device__ unsigned g_cnt[2][4][4];       // [layer][batch-tile][k-group] monotonic counters

// ---------------- helpers ----------------
__device__ __forceinline__ float tf32f(float x) {
    uint32_t u;
    asm("cvt.rna.tf32.f32 %0, %1;" : "=r"(u) : "f"(x));
    return __uint_as_float(u);
}

// pair-fragment mma: thread q supplies k-lanes (q, q+4); we feed it the
// adjacent pair (k0+2q, k0+2q+1) from BOTH operands -> dot product unchanged.
__device__ __forceinline__ void mma_tf32(float* c,
                                         float a0, float a1, float a2, float a3,
                                         float b0, float b1) {
    asm volatile(
        "mma.sync.aligned.m16n8k8.row.col.f32.tf32.tf32.f32 "
        "{%0,%1,%2,%3}, {%4,%5,%6,%7}, {%8,%9}, {%0,%1,%2,%3};\n"
        : "+f"(c[0]), "+f"(c[1]), "+f"(c[2]), "+f"(c[3])
        : "r"(__float_as_uint(a0)), "r"(__float_as_uint(a1)),
          "r"(__float_as_uint(a2)), "r"(__float_as_uint(a3)),
          "r"(__float_as_uint(b0)), "r"(__float_as_uint(b1)));
}

__device__ __forceinline__ float fsigm(float x) {
    return __fdividef(1.0f, 1.0f + __expf(-x));
}
__device__ __forceinline__ float ftanh(float x) {
    return 2.0f * __fdividef(1.0f, 1.0f + __expf(-2.0f * x)) - 1.0f;
}

__device__ __forceinline__ void cpasync16(uint32_t saddr, const void* g) {
    asm volatile("cp.async.cg.shared.global [%0], [%1], 16;\n" :: "r"(saddr), "l"(g));
}
__device__ __forceinline__ void cpasync_commit() {
    asm volatile("cp.async.commit_group;\n");
}
template <int N> __device__ __forceinline__ void cpasync_wait() {
    asm volatile("cp.async.wait_group %0;\n" :: "n"(N) : "memory");
}

__device__ __forceinline__ unsigned ld_acq(const unsigned* p) {
    unsigned v;
    asm volatile("ld.acquire.gpu.global.u32 %0, [%1];" : "=r"(v) : "l"(p) : "memory");
    return v;
}

__device__ __forceinline__ void wait_cnt(const unsigned* p, unsigned thr) {
    if (ld_acq(p) >= thr) return;
    while (ld_acq(p) < thr) __nanosleep(32);
}

// release-scoped signal: __syncthreads() gives intra-CTA happens-before;
// the release reduction publishes all prior CTA writes with L2 ordering,
// WITHOUT a full membar.gpu store-buffer drain.
__device__ __forceinline__ void signal_release(unsigned* p) {
    __syncthreads();
    if (threadIdx.x == 0)
        asm volatile("red.release.gpu.global.add.u32 [%0], %1;" :: "l"(p), "r"(1u) : "memory");
}

// ---------------- weight permute (gate interleave) + tf32 pre-round ----------------
__global__ void prep_kernel(const float* __restrict__ Wih0, const float* __restrict__ Whh0,
                            const float* __restrict__ bih0, const float* __restrict__ bhh0,
                            const float* __restrict__ Wih1, const float* __restrict__ Whh1,
                            const float* __restrict__ bih1, const float* __restrict__ bhh1) {
    int stride = gridDim.x * blockDim.x;
    int tid = blockIdx.x * blockDim.x + threadIdx.x;
    if (blockIdx.x == 0 && threadIdx.x < 32) {
        ((unsigned*)g_cnt)[threadIdx.x] = 0u;   // reset counters every replay
    }
    for (int i = tid; i < GG * HH; i += stride) {
        int orow = i / HH, k = i - orow * HH;
        int j = orow >> 2, gate = orow & 3;
        int src = (gate * HH + j) * HH + k;
        g_Whh[0][i] = tf32f(Whh0[src]);
        g_Whh[1][i] = tf32f(Whh1[src]);
        g_Wih1[i]   = tf32f(Wih1[src]);
    }
    for (int i = tid; i < GG * IND; i += stride) {
        int orow = i / IND, k = i - orow * IND;
        int j = orow >> 2, gate = orow & 3;
        g_Wih0[i] = tf32f(Wih0[(gate * HH + j) * IND + k]);
    }
    for (int i = tid; i < GG; i += stride) {
        int j = i >> 2, gate = i & 3;
        int src = gate * HH + j;
        g_bias[0][i] = bih0[src] + bhh0[src];
        g_bias[1][i] = bih1[src] + bhh1[src];
    }
}

// profiling-position dummy: makes scan_kernel<0> the 4th launch (ncu captures #4)
__global__ void dummy_kernel() {}

// ---------------- layer-0 input projection (K=64) ----------------
#define KC 64
__global__ void __launch_bounds__(256)
inproj0_kernel(const float* __restrict__ x) {
    __shared__ float sA[64][KC + 4];
    __shared__ float sB[64][KC + 4];

    const float* __restrict__ W    = g_Wih0;
    const float* __restrict__ bias = g_bias[0];

    int tid = threadIdx.x;
    int m0 = blockIdx.x * 64;
    int n0 = blockIdx.y * 64;
    int t  = m0 >> 8;
    int b0 = m0 & 255;
    const float* Abase = x + (size_t)b0 * TT * IND + (size_t)t * IND;

    int w = tid >> 5, lane = tid & 31, q = lane & 3, gq = lane >> 2;
    int wm = w & 3, wn = w >> 2;

    float acc[4][4] = {};

#pragma unroll
    for (int r = 0; r < 4; r++) {
        int idx = tid + r * 256;
        int row = idx >> 4;
        int c4  = idx & 15;
        float4 v = *reinterpret_cast<const float4*>(Abase + (size_t)row * TT * IND + c4 * 4);
        v.x = tf32f(v.x); v.y = tf32f(v.y); v.z = tf32f(v.z); v.w = tf32f(v.w);
        *reinterpret_cast<float4*>(&sA[row][c4 * 4]) = v;
        float4 wv = *reinterpret_cast<const float4*>(W + (long)(n0 + row) * IND + c4 * 4);
        *reinterpret_cast<float4*>(&sB[row][c4 * 4]) = wv;
    }
    __syncthreads();
#pragma unroll
    for (int ks = 0; ks < KC / 8; ks++) {
        int k0 = ks * 8;
        float a0 = sA[wm * 16 + gq    ][k0 + q];
        float a1 = sA[wm * 16 + gq + 8][k0 + q];
        float a2 = sA[wm * 16 + gq    ][k0 + q + 4];
        float a3 = sA[wm * 16 + gq + 8][k0 + q + 4];
#pragma unroll
        for (int nt = 0; nt < 4; nt++) {
            int n = wn * 32 + nt * 8 + gq;
            mma_tf32(acc[nt], a0, a1, a2, a3, sB[n][k0 + q], sB[n][k0 + q + 4]);
        }
    }

#pragma unroll
    for (int nt = 0; nt < 4; nt++) {
        int col = n0 + wn * 32 + nt * 8 + q * 2;
        float bv0 = bias[col], bv1 = bias[col + 1];
        int row = m0 + wm * 16 + gq;
        *reinterpret_cast<float2*>(g_xproj + (size_t)row * GG + col) =
            make_float2(acc[nt][0] + bv0, acc[nt][1] + bv1);
        *reinterpret_cast<float2*>(g_xproj + (size_t)(row + 8) * GG + col) =
            make_float2(acc[nt][2] + bv0, acc[nt][3] + bv1);
    }
}

// ---------------- layer-1 input projection: 128x128 CTA, 64x32 warps ----------------
#define IP_APAD 72
#define IP_TILEF (128 * IP_APAD)
#define IP2_SMEM (4 * IP_TILEF * 4)

__global__ void __launch_bounds__(256, 1)
inproj2_kernel() {
    extern __shared__ float sm[];
    float* sA[2] = { sm,                sm + IP_TILEF };
    float* sB[2] = { sm + 2 * IP_TILEF, sm + 3 * IP_TILEF };
    uint32_t sAu[2], sBu[2];
#pragma unroll
    for (int i = 0; i < 2; i++) {
        sAu[i] = (uint32_t)__cvta_generic_to_shared(sA[i]);
        sBu[i] = (uint32_t)__cvta_generic_to_shared(sB[i]);
    }

    int tid = threadIdx.x, w = tid >> 5, lane = tid & 31, q = lane & 3, gq = lane >> 2;
    int wm = w & 1, wn = w >> 1;
    int n0 = blockIdx.x * 128;
    long m0 = (long)blockIdx.y * 128;
    const float* Ab = g_hseq + m0 * HH;
    const float* Bb = g_Wih1 + (long)n0 * HH;

    float acc[4][4][4] = {};

#pragma unroll
    for (int r = 0; r < 8; r++) {
        int idx = tid + r * 256;
        int row = idx >> 4, c4 = idx & 15;
        cpasync16(sAu[0] + (row * IP_APAD + c4 * 4) * 4, Ab + (long)row * HH + c4 * 4);
        cpasync16(sBu[0] + (row * IP_APAD + c4 * 4) * 4, Bb + (long)row * HH + c4 * 4);
    }
    cpasync_commit();

    for (int ch = 0; ch < 8; ch++) {
        cpasync_wait<0>();
        __syncthreads();
        if (ch < 7) {
            int bi = (ch + 1) & 1;
#pragma unroll
            for (int r = 0; r < 8; r++) {
                int idx = tid + r * 256;
                int row = idx >> 4, c4 = idx & 15;
                cpasync16(sAu[bi] + (row * IP_APAD + c4 * 4) * 4,
                          Ab + (long)row * HH + (ch + 1) * 64 + c4 * 4);
                cpasync16(sBu[bi] + (row * IP_APAD + c4 * 4) * 4,
                          Bb + (long)row * HH + (ch + 1) * 64 + c4 * 4);
            }
            cpasync_commit();
        }
        const float* cA = sA[ch & 1] + (wm * 64) * IP_APAD;
        const float* cB = sB[ch & 1] + (wn * 32) * IP_APAD;
#pragma unroll
        for (int ks = 0; ks < 8; ks++) {
            int k2 = ks * 8 + 2 * q;
            float2 aL[4], aH[4];
#pragma unroll
            for (int mt = 0; mt < 4; mt++) {
                aL[mt] = *reinterpret_cast<const float2*>(cA + (mt * 16 + gq    ) * IP_APAD + k2);
                aH[mt] = *reinterpret_cast<const float2*>(cA + (mt * 16 + gq + 8) * IP_APAD + k2);
            }
#pragma unroll
            for (int nt = 0; nt < 4; nt++) {
                float2 bf = *reinterpret_cast<const float2*>(cB + (nt * 8 + gq) * IP_APAD + k2);
#pragma unroll
                for (int mt = 0; mt < 4; mt++)
                    mma_tf32(acc[mt][nt], aL[mt].x, aH[mt].x, aL[mt].y, aH[mt].y, bf.x, bf.y);
            }
        }
    }

#pragma unroll
    for (int nt = 0; nt < 4; nt++) {
        int col = n0 + wn * 32 + nt * 8 + q * 2;
        float bv0 = g_bias[1][col], bv1 = g_bias[1][col + 1];
#pragma unroll
        for (int mt = 0; mt < 4; mt++) {
            long row = m0 + wm * 64 + mt * 16 + gq;
            *reinterpret_cast<float2*>(g_xproj + row * GG + col) =
                make_float2(acc[mt][nt][0] + bv0, acc[mt][nt][1] + bv1);
            *reinterpret_cast<float2*>(g_xproj + (row + 8) * GG + col) =
                make_float2(acc[mt][nt][2] + bv0, acc[mt][nt][3] + bv1);
        }
    }
}

// ---------------- persistent LSTM scan: 256 threads, 8 warps of 32x16 tiles ----------------
// CTA (bi, ni): batch tile b0=64*bi, gate-column tile n0=64*ni (hidden j0=16*ni).
// Counters: g_cnt[L][bi][g] incremented by the 8 CTAs with ni in [8g, 8g+8);
// init counts as the first signal, so consumer threshold for step t is 8*(t+1).
#define WPAD 520
#define APAD 136
#define XPAD 68
#define GPAD 72
#define SW_F (64 * WPAD)
#define SA_F (64 * APAD)
#define XP_F (64 * XPAD)
#define SMEM_SCAN ((SW_F + 2 * SA_F + XP_F) * 4)

template <int LAYER>
__global__ void __launch_bounds__(256, 1)
scan_kernel() {
    extern __shared__ float sm[];
    float* sW  = sm;
    float* sA0 = sm + SW_F;
    float* sA1 = sA0 + SA_F;
    float* sXP = sA1 + SA_F;
    uint32_t sA0u = (uint32_t)__cvta_generic_to_shared(sA0);
    uint32_t sA1u = (uint32_t)__cvta_generic_to_shared(sA1);
    uint32_t sXPu = (uint32_t)__cvta_generic_to_shared(sXP);

    const float* __restrict__ Whh = g_Whh[LAYER];

    int tid = threadIdx.x, w = tid >> 5, lane = tid & 31, q = lane & 3, gq = lane >> 2;
    int wm = w & 1, wn = w >> 1;             // 8 warps: wm in {0,1} (32 rows), wn in 0..3 (16 cols)
    int bi = blockIdx.x & 3, ni = blockIdx.x >> 2;
    int b0 = bi * 64, n0 = ni * 64, j0 = ni * 16;

    unsigned* mycnt = &g_cnt[LAYER][bi][ni >> 3];
    const unsigned* cnt_b = g_cnt[LAYER][bi];

    // resident W slice: 64 rows x 512 K
    for (int i = tid; i < 64 * 128; i += 256) {
        int row = i >> 7, c4 = i & 127;
        *reinterpret_cast<float4*>(&sW[row * WPAD + c4 * 4]) =
            *reinterpret_cast<const float4*>(Whh + (long)(n0 + row) * HH + c4 * 4);
    }

    // zero-init my h slice (counts as production #1) + register c (4 units/thread)
    float c_reg[4];
#pragma unroll
    for (int s = 0; s < 4; s++) {
        c_reg[s] = 0.0f;
        int idx = tid + s * 256;
        int b = idx >> 4, j = idx & 15;
        g_hbuf[0][(b0 + b) * HH + j0 + j] = 0.0f;
    }
    signal_release(mycnt);

    for (int t = 0; t < TT; t++) {
        const float* __restrict__ hprev = g_hbuf[t & 1];
        float* __restrict__ hnew        = g_hbuf[(t + 1) & 1];
        const float* __restrict__ xp_t  = g_xproj + (size_t)t * BB * GG;
        float* __restrict__ hseq_t      = g_hseq + (size_t)t * BB * HH;
        const unsigned thr = 8u * (unsigned)(t + 1);   // 8 producers per counter + init

        float acc[2][2][4] = {};

        // xp tile prefetch (independent of h) into sXP
#pragma unroll
        for (int r = 0; r < 4; r++) {
            int idx = tid + r * 256;
            int row = idx >> 4, c4 = idx & 15;
            cpasync16(sXPu + (row * XPAD + c4 * 4) * 4,
                      xp_t + (size_t)(b0 + row) * GG + n0 + c4 * 4);
        }
        wait_cnt(&cnt_b[0], thr);
#pragma unroll
        for (int r = 0; r < 8; r++) {
            int idx = tid + r * 256;
            int row = idx >> 5, c4 = idx & 31;
            cpasync16(sA0u + (row * APAD + c4 * 4) * 4,
                      hprev + (size_t)(b0 + row) * HH + c4 * 4);
        }
        cpasync_commit();

#pragma unroll
        for (int ch = 0; ch < 4; ch++) {
            if (ch < 3) wait_cnt(&cnt_b[ch + 1], thr);   // detect before data wait
            cpasync_wait<0>();
            __syncthreads();
            if (ch < 3) {
                uint32_t dstu = ((ch + 1) & 1) ? sA1u : sA0u;
#pragma unroll
                for (int r = 0; r < 8; r++) {
                    int idx = tid + r * 256;
                    int row = idx >> 5, c4 = idx & 31;
                    cpasync16(dstu + (row * APAD + c4 * 4) * 4,
                              hprev + (size_t)(b0 + row) * HH + (ch + 1) * 128 + c4 * 4);
                }
                cpasync_commit();
            }
            const float* cA = ((ch & 1) ? sA1 : sA0) + (wm * 32) * APAD;
            const float* cW = sW + (wn * 16) * WPAD + ch * 128;
#pragma unroll 4
            for (int ks = 0; ks < 16; ks++) {
                int k2 = ks * 8 + 2 * q;
                float2 aL0 = *reinterpret_cast<const float2*>(cA + gq * APAD + k2);
                float2 aH0 = *reinterpret_cast<const float2*>(cA + (gq + 8) * APAD + k2);
                float2 aL1 = *reinterpret_cast<const float2*>(cA + (16 + gq) * APAD + k2);
                float2 aH1 = *reinterpret_cast<const float2*>(cA + (24 + gq) * APAD + k2);
#pragma unroll
                for (int nt = 0; nt < 2; nt++) {
                    float2 bf = *reinterpret_cast<const float2*>(cW + (nt * 8 + gq) * WPAD + k2);
                    mma_tf32(acc[0][nt], aL0.x, aH0.x, aL0.y, aH0.y, bf.x, bf.y);
                    mma_tf32(acc[1][nt], aL1.x, aH1.x, aL1.y, aH1.y, bf.x, bf.y);
                }
            }
        }

        // stage gate tile (i,f,g,o quadruples) into sA0 region
        float* Gm = sA0;
#pragma unroll
        for (int mt = 0; mt < 2; mt++)
#pragma unroll
            for (int nt = 0; nt < 2; nt++) {
                int row = wm * 32 + mt * 16 + gq;
                int col = wn * 16 + nt * 8 + q * 2;
                *reinterpret_cast<float2*>(&Gm[row * GPAD + col]) =
                    make_float2(acc[mt][nt][0], acc[mt][nt][1]);
                *reinterpret_cast<float2*>(&Gm[(row + 8) * GPAD + col]) =
                    make_float2(acc[mt][nt][2], acc[mt][nt][3]);
            }
        __syncthreads();

        float hv[4];
        int ci_s[4];
#pragma unroll
        for (int s = 0; s < 4; s++) {
            int idx = tid + s * 256;
            int b = idx >> 4, j = idx & 15;
            float4 gm = *reinterpret_cast<float4*>(&Gm[b * GPAD + j * 4]);
            float4 xp = *reinterpret_cast<float4*>(&sXP[b * XPAD + j * 4]);
            float ig = fsigm(gm.x + xp.x);
            float fg = fsigm(gm.y + xp.y);
            float gg = ftanh(gm.z + xp.z);
            float og = fsigm(gm.w + xp.w);
            float c = fg * c_reg[s] + ig * gg;
            float h = tf32f(og * ftanh(c));
            c_reg[s] = c;
            int ci = (b0 + b) * HH + j0 + j;
            hnew[ci] = h;
            hv[s] = h;
            ci_s[s] = ci;
        }

        // publish hnew with release semantics (no membar.gpu store-drain)
        signal_release(mycnt);

        // hseq stream (inproj2 input) AFTER the signal -- off the critical path
        if (LAYER == 0) {
#pragma unroll
            for (int s = 0; s < 4; s++) hseq_t[ci_s[s]] = hv[s];
        }
    }
}

// ---------------- output head: 32 CTAs, one warp per batch row ----------------
__global__ void __launch_bounds__(256)
final_kernel(const float* __restrict__ Wout, const float* __restrict__ bout,
             float* __restrict__ out) {
    __shared__ float sw[HH];
    int tid = threadIdx.x;
    for (int i = tid; i < HH; i += 256) sw[i] = Wout[i];
    __syncthreads();
    int wid = tid >> 5, lane = tid & 31;
    int row = blockIdx.x * 8 + wid;
    const float* h = g_hbuf[0];   // TT even -> last h in buffer 0
    float s = 0.0f;
#pragma unroll 4
    for (int j = lane; j < HH; j += 32) {
        float v = h[row * HH + j];
        v = v > 0.0f ? v : 0.0f;
        s += v * sw[j];
    }
#pragma unroll
    for (int o = 16; o > 0; o >>= 1) s += __shfl_xor_sync(0xFFFFFFFFu, s, o);
    if (lane == 0) out[row] = s + bout[0];
}

// ---------------- launch ----------------
extern "C" void kernel_launch(void* const* d_in, const int* in_sizes, int n_in,
                              void* d_out, int out_size) {
    (void)in_sizes; (void)n_in; (void)out_size;
    const float* x    = (const float*)d_in[0];
    const float* Wih0 = (const float*)d_in[1];
    const float* Whh0 = (const float*)d_in[2];
    const float* bih0 = (const float*)d_in[3];
    const float* bhh0 = (const float*)d_in[4];
    const float* Wih1 = (const float*)d_in[5];
    const float* Whh1 = (const float*)d_in[6];
    const float* bih1 = (const float*)d_in[7];
    const float* bhh1 = (const float*)d_in[8];
    const float* Wout = (const float*)d_in[9];
    const float* bout = (const float*)d_in[10];
    float* out = (float*)d_out;

    cudaFuncSetAttribute(scan_kernel<0>, cudaFuncAttributeMaxDynamicSharedMemorySize, SMEM_SCAN);
    cudaFuncSetAttribute(scan_kernel<1>, cudaFuncAttributeMaxDynamicSharedMemorySize, SMEM_SCAN);
    cudaFuncSetAttribute(inproj2_kernel, cudaFuncAttributeMaxDynamicSharedMemorySize, IP2_SMEM);

    prep_kernel<<<1024, 256>>>(Wih0, Whh0, bih0, bhh0, Wih1, Whh1, bih1, bhh1);  // launch 1
    inproj0_kernel<<<dim3(2048, 32), 256>>>(x);                                  // launch 2
    dummy_kernel<<<1, 32>>>();                                                   // launch 3
    scan_kernel<0><<<NCTA, 256, SMEM_SCAN>>>();                                  // launch 4 (ncu captures this)
    inproj2_kernel<<<dim3(16, 1024), 256, IP2_SMEM>>>();                         // launch 5
    scan_kernel<1><<<NCTA, 256, SMEM_SCAN>>>();                                  // launch 6
    final_kernel<<<32, 256>>>(Wout, bout, out);                                  // launch 7
}